// round 1
// baseline (speedup 1.0000x reference)
#include <cuda_runtime.h>
#include <cstdint>
#include <math.h>

#define NTOK 8192
#define CDIM 64
#define NEXP 16
#define CAP  640
#define NEC  ((size_t)NTOK * NEXP * CAP)       /* 83,886,080 elements */
#define SCALAR_OFF (2 * NEC)                   /* z, aux, std */
#define LOGITS_OFF (2 * NEC + 3)

// ---------------- scratch (no allocs allowed) ----------------
__device__ float              g_probs[NTOK * NEXP];
__device__ float              g_lse2[NTOK];
__device__ unsigned long long g_keys[NTOK];
__device__ int                g_expert[NTOK];
__device__ int                g_pos[NTOK];

// ---------------- kernel 1: pool + gate + softmax ----------------
// one block (64 threads) per token
__global__ void gating_kernel(const float* __restrict__ X,
                              const float* __restrict__ Wg,
                              const float* __restrict__ bg,
                              float* __restrict__ out_logits) {
    __shared__ float pooled[CDIM];
    __shared__ float lg[NEXP];
    int n = blockIdx.x;
    int c = threadIdx.x;  // 0..63

    // channel-mean over 8x8 spatial
    const float4* xp = (const float4*)(X + (size_t)n * (CDIM * 64) + (size_t)c * 64);
    float s = 0.f;
#pragma unroll
    for (int i = 0; i < 16; i++) {
        float4 v = xp[i];
        s += (v.x + v.y) + (v.z + v.w);
    }
    pooled[c] = s * (1.f / 64.f);
    __syncthreads();

    if (c < NEXP) {
        float d = bg[c];
#pragma unroll
        for (int k = 0; k < CDIM; k++) d += pooled[k] * Wg[k * NEXP + c];
        float l = d * (1.f / 1.5f);
        l = fminf(10.f, fmaxf(-10.f, l));
        lg[c] = l;
        out_logits[(size_t)n * NEXP + c] = l;
    }
    __syncthreads();

    if (c < 32) {  // warp 0 does softmax/argmax; lanes 0..15 carry data
        float v = (c < 16) ? lg[c] : -3.0e38f;
        float m = v;
        int   mi = c;
#pragma unroll
        for (int o = 8; o; o >>= 1) {
            float om = __shfl_xor_sync(0xffffffffu, m, o);
            int   oi = __shfl_xor_sync(0xffffffffu, mi, o);
            if (om > m || (om == m && oi < mi)) { m = om; mi = oi; }
        }
        float ev = (c < 16) ? expf(v - m) : 0.f;
        float sum = ev;
#pragma unroll
        for (int o = 8; o; o >>= 1) sum += __shfl_xor_sync(0xffffffffu, sum, o);
        if (c < 16) g_probs[n * NEXP + c] = ev / sum;
        if (c == 0) {
            float lse = m + logf(sum);
            g_lse2[n] = lse * lse;
            float pe = 1.f / sum;  // top-1 prob: exp(0)/sum
            g_expert[n] = mi;
            // sortable key: expert (4b) | prob bits (32b, positive float => monotonic) | 8191-n (stable tie-break)
            unsigned long long key = ((unsigned long long)mi << 45)
                                   | ((unsigned long long)__float_as_uint(pe) << 13)
                                   | (unsigned long long)(8191 - n);
            g_keys[n] = key;
        }
    }
}

// ---------------- kernel 2: per-expert rank (capacity position) ----------------
// 128 blocks x 256 threads; each warp handles 8 tokens; brute-force count over all keys
__global__ void rank_kernel() {
    __shared__ unsigned long long sk[4096];
    int t = threadIdx.x;
    int warp = t >> 5, lane = t & 31;
    int base = blockIdx.x * 64 + warp * 8;

    unsigned long long mykey[8], hi[8];
    int cnt[8];
#pragma unroll
    for (int q = 0; q < 8; q++) {
        mykey[q] = g_keys[base + q];
        hi[q] = ((mykey[q] >> 45) + 1ull) << 45;
        cnt[q] = 0;
    }
    for (int half = 0; half < 2; half++) {
        __syncthreads();
        for (int i = t; i < 4096; i += 256) sk[i] = g_keys[half * 4096 + i];
        __syncthreads();
        for (int j = lane; j < 4096; j += 32) {
            unsigned long long k = sk[j];
#pragma unroll
            for (int q = 0; q < 8; q++)
                cnt[q] += (int)((k > mykey[q]) & (k < hi[q]));
        }
    }
#pragma unroll
    for (int q = 0; q < 8; q++) {
        int csum = cnt[q];
#pragma unroll
        for (int o = 16; o; o >>= 1) csum += __shfl_xor_sync(0xffffffffu, csum, o);
        if (lane == 0) g_pos[base + q] = csum;
    }
}

// ---------------- kernel 3: scatter the one-hots ----------------
__global__ void scatter_kernel(float* __restrict__ out) {
    int n = blockIdx.x * blockDim.x + threadIdx.x;
    if (n >= NTOK) return;
    int pos = g_pos[n];
    if (pos < CAP) {
        size_t off = ((size_t)n * NEXP + g_expert[n]) * CAP + pos;
        out[off] = 1.f;        // dispatch
        out[NEC + off] = 1.f;  // combine (== dispatch for top-1 routing)
    }
}

// ---------------- kernel 4: scalar losses (deterministic reductions) ----------------
__global__ void finalize_kernel(const float* __restrict__ logits,
                                float* __restrict__ scal) {
    __shared__ float part[1024];
    __shared__ int   hist[NEXP];
    __shared__ float cs[NEXP];
    __shared__ float res_z, res_s1, res_s2;
    int t = threadIdx.x;

    if (t < NEXP) hist[t] = 0;
    __syncthreads();

    // per-expert surviving-token counts (integer atomics: deterministic)
    for (int i = t; i < NTOK; i += 1024)
        if (g_pos[i] < CAP) atomicAdd(&hist[g_expert[i]], 1);

    // per-expert prob column sums: thread t only ever touches column t&15
    float cp = 0.f;
    for (int i = t; i < NTOK * NEXP; i += 1024) cp += g_probs[i];
    part[t] = cp;
    __syncthreads();
    if (t < NEXP) {
        float s = 0.f;
        for (int k = t; k < 1024; k += NEXP) s += part[k];
        cs[t] = s;
    }
    __syncthreads();

    // z-loss: sum of lse^2
    float sz = 0.f;
    for (int i = t; i < NTOK; i += 1024) sz += g_lse2[i];
    part[t] = sz;
    __syncthreads();
    for (int o = 512; o; o >>= 1) { if (t < o) part[t] += part[t + o]; __syncthreads(); }
    if (t == 0) res_z = part[0];
    __syncthreads();

    // logits sum & sum of squares for std
    float s1 = 0.f, s2 = 0.f;
    for (int i = t; i < NTOK * NEXP; i += 1024) {
        float v = logits[i];
        s1 += v; s2 += v * v;
    }
    part[t] = s1;
    __syncthreads();
    for (int o = 512; o; o >>= 1) { if (t < o) part[t] += part[t + o]; __syncthreads(); }
    if (t == 0) res_s1 = part[0];
    __syncthreads();
    part[t] = s2;
    __syncthreads();
    for (int o = 512; o; o >>= 1) { if (t < o) part[t] += part[t + o]; __syncthreads(); }
    if (t == 0) res_s2 = part[0];
    __syncthreads();

    if (t == 0) {
        scal[0] = res_z / (float)NTOK;  // z_loss
        float aux = 0.f;
        for (int e = 0; e < NEXP; e++)
            aux += ((float)hist[e] / (float)NTOK) * (cs[e] / (float)NTOK);
        scal[1] = aux * (float)NEXP;    // aux_loss
        float inv = 1.f / (float)(NTOK * NEXP);
        float mean = res_s1 * inv;
        float var = res_s2 * inv - mean * mean;
        scal[2] = sqrtf(fmaxf(var, 0.f));  // logits_std
    }
}

// ---------------- launch ----------------
extern "C" void kernel_launch(void* const* d_in, const int* in_sizes, int n_in,
                              void* d_out, int out_size) {
    const float* X  = (const float*)d_in[0];
    const float* Wg = (const float*)d_in[1];
    const float* bg = (const float*)d_in[2];
    float* out = (float*)d_out;

    // zero dispatch+combine (672 MB) — everything else is written by kernels
    cudaMemsetAsync(out, 0, 2 * NEC * sizeof(float), 0);

    gating_kernel<<<NTOK, 64>>>(X, Wg, bg, out + LOGITS_OFF);
    rank_kernel<<<128, 256>>>();
    scatter_kernel<<<(NTOK + 255) / 256, 256>>>(out);
    finalize_kernel<<<1, 1024>>>(out + LOGITS_OFF, out + SCALAR_OFF);
}

// round 2
// speedup vs baseline: 1.0203x; 1.0203x over previous
#include <cuda_runtime.h>
#include <cstdint>
#include <math.h>

#define NTOK 8192
#define CDIM 64
#define NEXP 16
#define CAP  640
#define NEC  ((size_t)NTOK * NEXP * CAP)       /* 83,886,080 elements */
#define SCALAR_OFF (2 * NEC)                   /* z, aux, std */
#define LOGITS_OFF (2 * NEC + 3)

// ---------------- scratch (no allocs allowed) ----------------
__device__ float              g_probs[NTOK * NEXP];
__device__ float              g_lse2[NTOK];
__device__ unsigned long long g_keys[NTOK];
__device__ int                g_expert[NTOK];
__device__ int                g_pos[NTOK];

// ---------------- kernel 1: pool + gate + softmax ----------------
// one block (64 threads) per token
__global__ void gating_kernel(const float* __restrict__ X,
                              const float* __restrict__ Wg,
                              const float* __restrict__ bg,
                              float* __restrict__ out_logits) {
    __shared__ float pooled[CDIM];
    __shared__ float lg[NEXP];
    int n = blockIdx.x;
    int c = threadIdx.x;  // 0..63

    // channel-mean over 8x8 spatial
    const float4* xp = (const float4*)(X + (size_t)n * (CDIM * 64) + (size_t)c * 64);
    float s = 0.f;
#pragma unroll
    for (int i = 0; i < 16; i++) {
        float4 v = xp[i];
        s += (v.x + v.y) + (v.z + v.w);
    }
    pooled[c] = s * (1.f / 64.f);
    __syncthreads();

    if (c < NEXP) {
        float d = bg[c];
#pragma unroll
        for (int k = 0; k < CDIM; k++) d += pooled[k] * Wg[k * NEXP + c];
        float l = d * (1.f / 1.5f);
        l = fminf(10.f, fmaxf(-10.f, l));
        lg[c] = l;
        out_logits[(size_t)n * NEXP + c] = l;
    }
    __syncthreads();

    if (c < 32) {  // warp 0 does softmax/argmax; lanes 0..15 carry data
        float v = (c < 16) ? lg[c] : -3.0e38f;
        float m = v;
        int   mi = c;
#pragma unroll
        for (int o = 8; o; o >>= 1) {
            float om = __shfl_xor_sync(0xffffffffu, m, o);
            int   oi = __shfl_xor_sync(0xffffffffu, mi, o);
            if (om > m || (om == m && oi < mi)) { m = om; mi = oi; }
        }
        float ev = (c < 16) ? expf(v - m) : 0.f;
        float sum = ev;
#pragma unroll
        for (int o = 8; o; o >>= 1) sum += __shfl_xor_sync(0xffffffffu, sum, o);
        if (c < 16) g_probs[n * NEXP + c] = ev / sum;
        if (c == 0) {
            float lse = m + logf(sum);
            g_lse2[n] = lse * lse;
            float pe = 1.f / sum;  // top-1 prob: exp(0)/sum
            g_expert[n] = mi;
            // sortable key: expert (4b) | prob bits (32b, positive float => monotonic) | 8191-n (stable tie-break)
            unsigned long long key = ((unsigned long long)mi << 45)
                                   | ((unsigned long long)__float_as_uint(pe) << 13)
                                   | (unsigned long long)(8191 - n);
            g_keys[n] = key;
        }
    }
}

// ---------------- kernel 2: per-expert rank (capacity position) ----------------
// 128 blocks x 256 threads; each warp handles 8 tokens; brute-force count over all keys
__global__ void rank_kernel() {
    __shared__ unsigned long long sk[4096];
    int t = threadIdx.x;
    int warp = t >> 5, lane = t & 31;
    int base = blockIdx.x * 64 + warp * 8;

    unsigned long long mykey[8], hi[8];
    int cnt[8];
#pragma unroll
    for (int q = 0; q < 8; q++) {
        mykey[q] = g_keys[base + q];
        hi[q] = ((mykey[q] >> 45) + 1ull) << 45;
        cnt[q] = 0;
    }
    for (int half = 0; half < 2; half++) {
        __syncthreads();
        for (int i = t; i < 4096; i += 256) sk[i] = g_keys[half * 4096 + i];
        __syncthreads();
        for (int j = lane; j < 4096; j += 32) {
            unsigned long long k = sk[j];
#pragma unroll
            for (int q = 0; q < 8; q++)
                cnt[q] += (int)((k > mykey[q]) & (k < hi[q]));
        }
    }
#pragma unroll
    for (int q = 0; q < 8; q++) {
        int csum = cnt[q];
#pragma unroll
        for (int o = 16; o; o >>= 1) csum += __shfl_xor_sync(0xffffffffu, csum, o);
        if (lane == 0) g_pos[base + q] = csum;
    }
}

// ---------------- kernel 3: scatter the one-hots ----------------
__global__ void scatter_kernel(float* __restrict__ out) {
    int n = blockIdx.x * blockDim.x + threadIdx.x;
    if (n >= NTOK) return;
    int pos = g_pos[n];
    if (pos < CAP) {
        size_t off = ((size_t)n * NEXP + g_expert[n]) * CAP + pos;
        out[off] = 1.f;        // dispatch
        out[NEC + off] = 1.f;  // combine (== dispatch for top-1 routing)
    }
}

// ---------------- kernel 4: scalar losses (deterministic reductions) ----------------
__global__ void finalize_kernel(const float* __restrict__ logits,
                                float* __restrict__ scal) {
    __shared__ float part[1024];
    __shared__ int   hist[NEXP];
    __shared__ float cs[NEXP];
    __shared__ float res_z, res_s1, res_s2;
    int t = threadIdx.x;

    if (t < NEXP) hist[t] = 0;
    __syncthreads();

    // per-expert surviving-token counts (integer atomics: deterministic)
    for (int i = t; i < NTOK; i += 1024)
        if (g_pos[i] < CAP) atomicAdd(&hist[g_expert[i]], 1);

    // per-expert prob column sums: thread t only ever touches column t&15
    float cp = 0.f;
    for (int i = t; i < NTOK * NEXP; i += 1024) cp += g_probs[i];
    part[t] = cp;
    __syncthreads();
    if (t < NEXP) {
        float s = 0.f;
        for (int k = t; k < 1024; k += NEXP) s += part[k];
        cs[t] = s;
    }
    __syncthreads();

    // z-loss: sum of lse^2
    float sz = 0.f;
    for (int i = t; i < NTOK; i += 1024) sz += g_lse2[i];
    part[t] = sz;
    __syncthreads();
    for (int o = 512; o; o >>= 1) { if (t < o) part[t] += part[t + o]; __syncthreads(); }
    if (t == 0) res_z = part[0];
    __syncthreads();

    // logits sum & sum of squares for std
    float s1 = 0.f, s2 = 0.f;
    for (int i = t; i < NTOK * NEXP; i += 1024) {
        float v = logits[i];
        s1 += v; s2 += v * v;
    }
    part[t] = s1;
    __syncthreads();
    for (int o = 512; o; o >>= 1) { if (t < o) part[t] += part[t + o]; __syncthreads(); }
    if (t == 0) res_s1 = part[0];
    __syncthreads();
    part[t] = s2;
    __syncthreads();
    for (int o = 512; o; o >>= 1) { if (t < o) part[t] += part[t + o]; __syncthreads(); }
    if (t == 0) res_s2 = part[0];
    __syncthreads();

    if (t == 0) {
        scal[0] = res_z / (float)NTOK;  // z_loss
        float aux = 0.f;
        for (int e = 0; e < NEXP; e++)
            aux += ((float)hist[e] / (float)NTOK) * (cs[e] / (float)NTOK);
        scal[1] = aux * (float)NEXP;    // aux_loss
        float inv = 1.f / (float)(NTOK * NEXP);
        float mean = res_s1 * inv;
        float var = res_s2 * inv - mean * mean;
        scal[2] = sqrtf(fmaxf(var, 0.f));  // logits_std
    }
}

// ---------------- launch: fork memset onto a side stream ----------------
extern "C" void kernel_launch(void* const* d_in, const int* in_sizes, int n_in,
                              void* d_out, int out_size) {
    const float* X  = (const float*)d_in[0];
    const float* Wg = (const float*)d_in[1];
    const float* bg = (const float*)d_in[2];
    float* out = (float*)d_out;

    // One-time host-side resource creation (streams/events: no device memory).
    // Identical GPU work is enqueued on every call.
    static cudaStream_t s_side = nullptr;
    static cudaEvent_t  ev_start = nullptr, ev_rank = nullptr, ev_done = nullptr;
    if (s_side == nullptr) {
        cudaStreamCreateWithFlags(&s_side, cudaStreamNonBlocking);
        cudaEventCreateWithFlags(&ev_start, cudaEventDisableTiming);
        cudaEventCreateWithFlags(&ev_rank,  cudaEventDisableTiming);
        cudaEventCreateWithFlags(&ev_done,  cudaEventDisableTiming);
    }

    // Fork: side stream zeros the 672MB dispatch+combine region while the
    // capture stream runs the compute chain (disjoint memory).
    cudaEventRecord(ev_start, 0);
    cudaStreamWaitEvent(s_side, ev_start, 0);
    cudaMemsetAsync(out, 0, 2 * NEC * sizeof(float), s_side);

    // Compute chain on capture stream (writes logits + scalars at out tail,
    // outside the memset range).
    gating_kernel<<<NTOK, 64>>>(X, Wg, bg, out + LOGITS_OFF);
    rank_kernel<<<128, 256>>>();
    cudaEventRecord(ev_rank, 0);
    finalize_kernel<<<1, 1024>>>(out + LOGITS_OFF, out + SCALAR_OFF);

    // Side stream: once ranks are known AND zeroing finished, scatter the ones.
    cudaStreamWaitEvent(s_side, ev_rank, 0);
    scatter_kernel<<<(NTOK + 255) / 256, 256, 0, s_side>>>(out);
    cudaEventRecord(ev_done, s_side);

    // Join back onto the capture stream.
    cudaStreamWaitEvent(0, ev_done, 0);
}